// round 9
// baseline (speedup 1.0000x reference)
#include <cuda_runtime.h>
#include <cuda_fp16.h>
#include <cstdint>

// ---------------------------------------------------------------- constants
#define HH 80
#define WW 80
#define CH 256
#define NC 22
#define DIM 256
#define P 25600              // 4*80*80 pixels
#define NCHUNK 36            // 9 taps * 4 chunks of 64 channels
// stage layout: A 16K | B 8K
#define STAGE 24576
#define NSTAGE 2

// device scratch
__device__ uint32_t g_selh2[P * 9];    // sel*norm as broadcast half2
__device__ uint4 g_w[144 * 512];       // weight fp16 smem-images (pre-swizzled 8KB blocks)
__device__ uint4 g_xf[4 * P * 8];      // x fp16, [ct][p][g] 16B groups

// ---------------------------------------------------------------- helpers
static __device__ __forceinline__ uint32_t smem_u32(const void* p) {
    uint32_t a;
    asm("{ .reg .u64 t; cvta.to.shared.u64 t, %1; cvt.u32.u64 %0, t; }" : "=r"(a) : "l"(p));
    return a;
}

#define LDSM4(r, addr) \
    asm volatile("ldmatrix.sync.aligned.m8n8.x4.shared.b16 {%0,%1,%2,%3},[%4];" \
        : "=r"((r)[0]), "=r"((r)[1]), "=r"((r)[2]), "=r"((r)[3]) : "r"(addr))
#define MMA(acc, a, b) \
    asm volatile("mma.sync.aligned.m16n8k16.row.col.f32.f16.f16.f32 " \
        "{%0,%1,%2,%3},{%4,%5,%6,%7},{%8,%9},{%0,%1,%2,%3};" \
        : "+f"((acc)[0]), "+f"((acc)[1]), "+f"((acc)[2]), "+f"((acc)[3]) \
        : "r"((a)[0]), "r"((a)[1]), "r"((a)[2]), "r"((a)[3]), "r"((b)[0]), "r"((b)[1]))
#define CPA(dst, src) \
    asm volatile("cp.async.cg.shared.global [%0], [%1], 16;" :: "r"(dst), "l"(src))

static __device__ __forceinline__ uint32_t hmul2u(uint32_t a, uint32_t s) {
    uint32_t r;
    asm("mul.rn.f16x2 %0, %1, %2;" : "=r"(r) : "r"(a), "r"(s));
    return r;
}

// ---------------------------------------------------------------- fused prep kernel
// blocks [0,400): selnorm (4 lanes/pixel) -> g_selh2
// blocks [400,3600): x -> fp16
// blocks [3600,3888): weight -> fp16 smem-image
__global__ void prep_all(const float* __restrict__ x,
                         const float* __restrict__ seg,
                         const float* __restrict__ wgt)
{
    int b = blockIdx.x;
    if (b < 400) {
        // ---- selnorm ----
        int gid = b * 256 + threadIdx.x;       // P*4 threads
        int p = gid >> 2, q = gid & 3;
        int w = p % WW, h = (p / WW) % HH;
        int c0 = q * 6;
        int ncl = (q == 3) ? 4 : 6;

        const float* cp_ = seg + (size_t)p * NC + c0;
        float cv[6];
#pragma unroll
        for (int i = 0; i < 6; i++) cv[i] = (i < ncl) ? cp_[i] : -1e30f;

        float m = cv[0];
#pragma unroll
        for (int i = 1; i < 6; i++) m = fmaxf(m, cv[i]);
        m = fmaxf(m, __shfl_xor_sync(0xffffffffu, m, 1));
        m = fmaxf(m, __shfl_xor_sync(0xffffffffu, m, 2));

        float sel[9];
        int cnt = 0;
#pragma unroll
        for (int k = 0; k < 9; k++) {
            int dh = k / 3 - 1, dw = k % 3 - 1;
            int hh = h + dh, ww = w + dw;
            float s = 0.0f;
            if (hh >= 0 && hh < HH && ww >= 0 && ww < WW) {
                const float* nb = seg + (size_t)(p + dh * WW + dw) * NC + c0;
#pragma unroll
                for (int i = 0; i < 6; i++)
                    if (i < ncl && cv[i] == m) s += nb[i];
            }
            s += __shfl_xor_sync(0xffffffffu, s, 1);
            s += __shfl_xor_sync(0xffffffffu, s, 2);
            sel[k] = s;
            if (s != 0.0f) cnt++;
        }
        float nrm = (cnt > 0) ? 9.0f / (float)cnt : 0.0f;
        for (int k = q; k < 9; k += 4) {
            __half hv = __float2half_rn(sel[k] * nrm);
            uint32_t u = (uint32_t)__half_as_ushort(hv);
            g_selh2[p * 9 + k] = u | (u << 16);
        }
    } else if (b < 3600) {
        // ---- x -> fp16 ----
        int gid = (b - 400) * 256 + threadIdx.x;   // P*32 threads
        int g8 = gid & 31;
        int p  = gid >> 5;
        int c0 = g8 * 8;
        int ct = c0 >> 6, g = (c0 >> 3) & 7;

        const float* src = x + (size_t)p * CH + c0;
        uint32_t h4[4];
#pragma unroll
        for (int j = 0; j < 4; j++) {
            __half h0 = __float2half_rn(src[2*j]);
            __half h1 = __float2half_rn(src[2*j+1]);
            h4[j] = (uint32_t)__half_as_ushort(h0) | ((uint32_t)__half_as_ushort(h1) << 16);
        }
        g_xf[(ct * P + p) * 8 + g] = make_uint4(h4[0], h4[1], h4[2], h4[3]);
    } else {
        // ---- weight -> fp16 pre-swizzled image ----
        int id = (b - 3600) * 256 + threadIdx.x;   // 73728 threads
        int cc8  = id & 7;
        int row  = (id >> 3) & 63;
        int blk  = id >> 9;            // 0..143
        int nb4  = blk & 3;
        int chunk = blk >> 2;
        int ktap = chunk >> 2, ct = chunk & 3;
        int d  = nb4 * 64 + row;
        int c0 = ct * 64 + cc8 * 8;

        uint32_t h4[4];
#pragma unroll
        for (int j = 0; j < 4; j++) {
            float v0 = wgt[(size_t)(c0 + 2*j)     * (9 * DIM) + ktap * DIM + d];
            float v1 = wgt[(size_t)(c0 + 2*j + 1) * (9 * DIM) + ktap * DIM + d];
            __half h0 = __float2half_rn(v0);
            __half h1 = __float2half_rn(v1);
            h4[j] = (uint32_t)__half_as_ushort(h0) | ((uint32_t)__half_as_ushort(h1) << 16);
        }
        int idx = blk * 512 + row * 8 + (cc8 ^ (row & 7));
        g_w[idx] = make_uint4(h4[0], h4[1], h4[2], h4[3]);
    }
}

// ---------------------------------------------------------------- HMMA implicit GEMM
// CTA 128(M) x 64(N), 256 threads, 8 warps (4M x 2N), warp tile 32x32.
// sel folded at A-fill time; inner loop pure ldmatrix + MMA; B via cp.async.
// 3 CTAs/SM, 2-stage pipeline -> 800 CTAs / 444 slots = 1.8 waves.
__global__ __launch_bounds__(256, 3) void pconv_mma(float* __restrict__ out)
{
    extern __shared__ __align__(1024) char smem[];
    const uint32_t sb = smem_u32(smem);
    const int tid = threadIdx.x, wid = tid >> 5, lid = tid & 31;
    const int p0 = blockIdx.x * 128;
    const int nblk = blockIdx.y;            // 0..3 (64-wide N block)
    const int wm = wid & 3, wn = wid >> 2;  // 4 M-quarters x 2 N-halves(32)

    // ldmatrix lane addressing
    const int arow = wm * 32 + (lid & 15);
    const int achp = lid >> 4;
    const int bi = lid >> 3;                   // 0..3
    const int bnt = bi >> 1, bkh = bi & 1;
    const int brow = wn * 32 + bnt * 8 + (lid & 7);
    const int bsw  = lid & 7;

    float acc[2][4][4];
#pragma unroll
    for (int i = 0; i < 2; i++)
#pragma unroll
        for (int j = 0; j < 4; j++)
#pragma unroll
            for (int r = 0; r < 4; r++) acc[i][j][r] = 0.0f;

    // A prefetch registers (one chunk ahead)
    uint4 aR[4];
    uint32_t sR[4];

    auto ldgA = [&](int chunk) {
        int ktap = chunk >> 2, ct = chunk & 3;
        int delta = (ktap / 3 - 1) * WW + (ktap % 3 - 1);
#pragma unroll
        for (int i = 0; i < 4; i++) {
            int u = tid + i * 256;
            int fr = u >> 3, fg = u & 7;
            int nb = p0 + fr + delta; nb = nb < 0 ? 0 : (nb >= P ? P - 1 : nb);
            aR[i] = g_xf[(ct * P + nb) * 8 + (fg ^ (nb & 7))];
            sR[i] = g_selh2[(p0 + fr) * 9 + ktap];
        }
    };
    auto stsA = [&](int s) {
        char* st = smem + s * STAGE;
#pragma unroll
        for (int i = 0; i < 4; i++) {
            int u = tid + i * 256;
            int fr = u >> 3, fg = u & 7;
            uint4 v = aR[i];
            v.x = hmul2u(v.x, sR[i]);
            v.y = hmul2u(v.y, sR[i]);
            v.z = hmul2u(v.z, sR[i]);
            v.w = hmul2u(v.w, sR[i]);
            *(uint4*)(st + fr * 128 + fg * 16) = v;
        }
    };
    auto cpB = [&](int chunk, int s) {
        uint32_t st = sb + s * STAGE;
        const uint4* wp = g_w + (size_t)(chunk * 4 + nblk) * 512;
        CPA(st + 16384 + tid * 16,         wp + tid);
        CPA(st + 16384 + (tid + 256) * 16, wp + tid + 256);
        asm volatile("cp.async.commit_group;" ::: "memory");
    };

    auto compute = [&](int chunk, int s) {
        uint32_t st = sb + s * STAGE;
        int ktap = chunk >> 2;
        int delta = (ktap / 3 - 1) * WW + (ktap % 3 - 1);
        int asw = (arow + delta + 128) & 7;       // tap-shifted swizzle phase
        uint32_t Ap = st, Bp = st + 16384;
#pragma unroll
        for (int ks = 0; ks < 4; ks++) {
            uint32_t a[2][4], bfr[4][2];
#pragma unroll
            for (int mt = 0; mt < 2; mt++) {
                uint32_t off = (uint32_t)(arow + mt * 16) * 128
                             + (((ks * 2 + achp) ^ asw) << 4);
                LDSM4(a[mt], Ap + off);
            }
#pragma unroll
            for (int ntp = 0; ntp < 2; ntp++) {
                uint32_t off = (uint32_t)(brow + ntp * 16) * 128
                             + (((ks * 2 + bkh) ^ bsw) << 4);
                uint32_t r[4];
                LDSM4(r, Bp + off);
                bfr[ntp*2+0][0] = r[0]; bfr[ntp*2+0][1] = r[1];
                bfr[ntp*2+1][0] = r[2]; bfr[ntp*2+1][1] = r[3];
            }
#pragma unroll
            for (int mt = 0; mt < 2; mt++)
#pragma unroll
                for (int nt = 0; nt < 4; nt++)
                    MMA(acc[mt][nt], a[mt], bfr[nt]);
        }
    };

    // prologue: stage 0 filled, A(1) in regs
    ldgA(0);
    stsA(0);
    cpB(0, 0);
    ldgA(1);
    asm volatile("cp.async.wait_group 0;" ::: "memory");
    __syncthreads();

#pragma unroll 1
    for (int c = 0; c < NCHUNK; c++) {
        int s = c & 1;
        if (c + 1 < NCHUNK) cpB(c + 1, s ^ 1);     // B async into other stage
        compute(c, s);
        if (c + 1 < NCHUNK) {
            stsA(s ^ 1);                           // sel-folded A for c+1
            if (c + 2 < NCHUNK) ldgA(c + 2);       // prefetch next A into regs
            asm volatile("cp.async.wait_group 0;" ::: "memory");
        }
        __syncthreads();
    }

    // epilogue
#pragma unroll
    for (int mt = 0; mt < 2; mt++) {
        int r0 = p0 + wm * 32 + mt * 16 + (lid >> 2);
#pragma unroll
        for (int nt = 0; nt < 4; nt++) {
            int col = nblk * 64 + wn * 32 + nt * 8 + (lid & 3) * 2;
            float2* d0 = (float2*)(out + (size_t)r0 * DIM + col);
            float2* d1 = (float2*)(out + (size_t)(r0 + 8) * DIM + col);
            *d0 = make_float2(acc[mt][nt][0], acc[mt][nt][1]);
            *d1 = make_float2(acc[mt][nt][2], acc[mt][nt][3]);
        }
    }
}

// ---------------------------------------------------------------- launch
extern "C" void kernel_launch(void* const* d_in, const int* in_sizes, int n_in,
                              void* d_out, int out_size)
{
    const float* x   = (const float*)d_in[0];
    const float* seg = (const float*)d_in[1];
    const float* wgt = (const float*)d_in[2];
    float* out = (float*)d_out;

    cudaFuncSetAttribute(pconv_mma, cudaFuncAttributeMaxDynamicSharedMemorySize,
                         NSTAGE * STAGE);

    prep_all<<<3888, 256>>>(x, seg, wgt);

    dim3 grid(P / 128, 4);
    pconv_mma<<<grid, 256, NSTAGE * STAGE>>>(out);
}

// round 10
// speedup vs baseline: 1.2705x; 1.2705x over previous
#include <cuda_runtime.h>
#include <cuda_fp16.h>
#include <cstdint>

// ---------------------------------------------------------------- constants
#define HH 80
#define WW 80
#define CH 256
#define NC 22
#define DIM 256
#define P 25600              // 4*80*80 pixels
#define NCHUNK 36            // 9 taps * 4 chunks of 64 channels
// stage layout: A 8K | B 16K
#define STAGE 24576
#define NSTAGE 2

// device scratch
__device__ uint32_t g_selh2[P * 9];    // sel*norm as broadcast half2
__device__ uint4 g_w[144 * 512];       // weight fp16 smem-images (pre-swizzled 8KB blocks)
__device__ uint4 g_xf[4 * P * 8];      // x fp16, [ct][p][g] 16B groups

// ---------------------------------------------------------------- helpers
static __device__ __forceinline__ uint32_t smem_u32(const void* p) {
    uint32_t a;
    asm("{ .reg .u64 t; cvta.to.shared.u64 t, %1; cvt.u32.u64 %0, t; }" : "=r"(a) : "l"(p));
    return a;
}

#define LDSM4(r, addr) \
    asm volatile("ldmatrix.sync.aligned.m8n8.x4.shared.b16 {%0,%1,%2,%3},[%4];" \
        : "=r"((r)[0]), "=r"((r)[1]), "=r"((r)[2]), "=r"((r)[3]) : "r"(addr))
#define MMA(acc, a, b) \
    asm volatile("mma.sync.aligned.m16n8k16.row.col.f32.f16.f16.f32 " \
        "{%0,%1,%2,%3},{%4,%5,%6,%7},{%8,%9},{%0,%1,%2,%3};" \
        : "+f"((acc)[0]), "+f"((acc)[1]), "+f"((acc)[2]), "+f"((acc)[3]) \
        : "r"((a)[0]), "r"((a)[1]), "r"((a)[2]), "r"((a)[3]), "r"((b)[0]), "r"((b)[1]))
#define CPA(dst, src) \
    asm volatile("cp.async.cg.shared.global [%0], [%1], 16;" :: "r"(dst), "l"(src))

static __device__ __forceinline__ uint32_t hmul2u(uint32_t a, uint32_t s) {
    uint32_t r;
    asm("mul.rn.f16x2 %0, %1, %2;" : "=r"(r) : "r"(a), "r"(s));
    return r;
}

// ---------------------------------------------------------------- fused prep kernel
// blocks [0,400): selnorm (4 lanes/pixel) -> g_selh2
// blocks [400,3600): x -> fp16
// blocks [3600,3888): weight -> fp16 smem-image
__global__ void prep_all(const float* __restrict__ x,
                         const float* __restrict__ seg,
                         const float* __restrict__ wgt)
{
    int b = blockIdx.x;
    if (b < 400) {
        // ---- selnorm ----
        int gid = b * 256 + threadIdx.x;       // P*4 threads
        int p = gid >> 2, q = gid & 3;
        int w = p % WW, h = (p / WW) % HH;
        int c0 = q * 6;
        int ncl = (q == 3) ? 4 : 6;

        const float* cp_ = seg + (size_t)p * NC + c0;
        float cv[6];
#pragma unroll
        for (int i = 0; i < 6; i++) cv[i] = (i < ncl) ? cp_[i] : -1e30f;

        float m = cv[0];
#pragma unroll
        for (int i = 1; i < 6; i++) m = fmaxf(m, cv[i]);
        m = fmaxf(m, __shfl_xor_sync(0xffffffffu, m, 1));
        m = fmaxf(m, __shfl_xor_sync(0xffffffffu, m, 2));

        float sel[9];
        int cnt = 0;
#pragma unroll
        for (int k = 0; k < 9; k++) {
            int dh = k / 3 - 1, dw = k % 3 - 1;
            int hh = h + dh, ww = w + dw;
            float s = 0.0f;
            if (hh >= 0 && hh < HH && ww >= 0 && ww < WW) {
                const float* nb = seg + (size_t)(p + dh * WW + dw) * NC + c0;
#pragma unroll
                for (int i = 0; i < 6; i++)
                    if (i < ncl && cv[i] == m) s += nb[i];
            }
            s += __shfl_xor_sync(0xffffffffu, s, 1);
            s += __shfl_xor_sync(0xffffffffu, s, 2);
            sel[k] = s;
            if (s != 0.0f) cnt++;
        }
        float nrm = (cnt > 0) ? 9.0f / (float)cnt : 0.0f;
        for (int k = q; k < 9; k += 4) {
            __half hv = __float2half_rn(sel[k] * nrm);
            uint32_t u = (uint32_t)__half_as_ushort(hv);
            g_selh2[p * 9 + k] = u | (u << 16);
        }
    } else if (b < 3600) {
        // ---- x -> fp16 ----
        int gid = (b - 400) * 256 + threadIdx.x;   // P*32 threads
        int g8 = gid & 31;
        int p  = gid >> 5;
        int c0 = g8 * 8;
        int ct = c0 >> 6, g = (c0 >> 3) & 7;

        const float* src = x + (size_t)p * CH + c0;
        uint32_t h4[4];
#pragma unroll
        for (int j = 0; j < 4; j++) {
            __half h0 = __float2half_rn(src[2*j]);
            __half h1 = __float2half_rn(src[2*j+1]);
            h4[j] = (uint32_t)__half_as_ushort(h0) | ((uint32_t)__half_as_ushort(h1) << 16);
        }
        g_xf[(ct * P + p) * 8 + g] = make_uint4(h4[0], h4[1], h4[2], h4[3]);
    } else {
        // ---- weight -> fp16 pre-swizzled image ----
        int id = (b - 3600) * 256 + threadIdx.x;   // 73728 threads
        int cc8  = id & 7;
        int row  = (id >> 3) & 63;
        int blk  = id >> 9;            // 0..143
        int nb4  = blk & 3;
        int chunk = blk >> 2;
        int ktap = chunk >> 2, ct = chunk & 3;
        int d  = nb4 * 64 + row;
        int c0 = ct * 64 + cc8 * 8;

        uint32_t h4[4];
#pragma unroll
        for (int j = 0; j < 4; j++) {
            float v0 = wgt[(size_t)(c0 + 2*j)     * (9 * DIM) + ktap * DIM + d];
            float v1 = wgt[(size_t)(c0 + 2*j + 1) * (9 * DIM) + ktap * DIM + d];
            __half h0 = __float2half_rn(v0);
            __half h1 = __float2half_rn(v1);
            h4[j] = (uint32_t)__half_as_ushort(h0) | ((uint32_t)__half_as_ushort(h1) << 16);
        }
        int idx = blk * 512 + row * 8 + (cc8 ^ (row & 7));
        g_w[idx] = make_uint4(h4[0], h4[1], h4[2], h4[3]);
    }
}

// ---------------------------------------------------------------- HMMA implicit GEMM
// CTA 64(M) x 128(N), 128 threads, 4 warps (2M x 2N), warp tile 32x64.
// sel folded at A-fill time; inner loop pure ldmatrix + MMA; B via cp.async.
// 3 CTAs/SM -> 800 CTAs / 444 slots = 1.80 waves (util ~0.90).
__global__ __launch_bounds__(128, 3) void pconv_mma(float* __restrict__ out)
{
    extern __shared__ __align__(1024) char smem[];
    const uint32_t sb = smem_u32(smem);
    const int tid = threadIdx.x, wid = tid >> 5, lid = tid & 31;
    const int p0 = blockIdx.x * 64;
    const int nblk = blockIdx.y;            // 0..1 (128-wide N block)
    const int wm = wid & 1, wn = wid >> 1;  // 2 M-halves x 2 N-halves(64)

    // ldmatrix lane addressing
    const int arow = wm * 32 + (lid & 15);
    const int achp = lid >> 4;
    const int bi = lid >> 3;                   // 0..3
    const int bnt = bi >> 1, bkh = bi & 1;
    const int brow = wn * 64 + bnt * 8 + (lid & 7);
    const int bsw  = lid & 7;

    float acc[2][8][4];
#pragma unroll
    for (int i = 0; i < 2; i++)
#pragma unroll
        for (int j = 0; j < 8; j++)
#pragma unroll
            for (int r = 0; r < 4; r++) acc[i][j][r] = 0.0f;

    // A prefetch registers (one chunk ahead): 512 uint4 over 128 threads = 4
    uint4 aR[4];
    uint32_t sR[4];

    auto ldgA = [&](int chunk) {
        int ktap = chunk >> 2, ct = chunk & 3;
        int delta = (ktap / 3 - 1) * WW + (ktap % 3 - 1);
#pragma unroll
        for (int i = 0; i < 4; i++) {
            int u = tid + i * 128;
            int fr = u >> 3, fg = u & 7;
            int nb = p0 + fr + delta; nb = nb < 0 ? 0 : (nb >= P ? P - 1 : nb);
            aR[i] = g_xf[(ct * P + nb) * 8 + (fg ^ (nb & 7))];
            sR[i] = g_selh2[(p0 + fr) * 9 + ktap];
        }
    };
    auto stsA = [&](int s) {
        char* st = smem + s * STAGE;
#pragma unroll
        for (int i = 0; i < 4; i++) {
            int u = tid + i * 128;
            int fr = u >> 3, fg = u & 7;
            uint4 v = aR[i];
            v.x = hmul2u(v.x, sR[i]);
            v.y = hmul2u(v.y, sR[i]);
            v.z = hmul2u(v.z, sR[i]);
            v.w = hmul2u(v.w, sR[i]);
            *(uint4*)(st + fr * 128 + fg * 16) = v;
        }
    };
    auto cpB = [&](int chunk, int s) {
        uint32_t st = sb + s * STAGE;
        const uint4* wp = g_w + (size_t)(chunk * 4 + nblk * 2) * 512;
#pragma unroll
        for (int i = 0; i < 8; i++)
            CPA(st + 8192 + (tid + i * 128) * 16, wp + tid + i * 128);
        asm volatile("cp.async.commit_group;" ::: "memory");
    };

    auto compute = [&](int chunk, int s) {
        uint32_t st = sb + s * STAGE;
        int ktap = chunk >> 2;
        int delta = (ktap / 3 - 1) * WW + (ktap % 3 - 1);
        int asw = (arow + delta + 128) & 7;       // tap-shifted swizzle phase
        uint32_t Ap = st, Bp = st + 8192;
#pragma unroll
        for (int ks = 0; ks < 4; ks++) {
            uint32_t a[2][4], bfr[8][2];
            {
                uint32_t off0 = (uint32_t)arow * 128 + (((ks * 2 + achp) ^ asw) << 4);
                LDSM4(a[0], Ap + off0);
            }
#pragma unroll
            for (int ntp = 0; ntp < 4; ntp++) {
                uint32_t off = (uint32_t)(brow + ntp * 16) * 128
                             + (((ks * 2 + bkh) ^ bsw) << 4);
                uint32_t r[4];
                LDSM4(r, Bp + off);
                bfr[ntp*2+0][0] = r[0]; bfr[ntp*2+0][1] = r[1];
                bfr[ntp*2+1][0] = r[2]; bfr[ntp*2+1][1] = r[3];
            }
            // a[1] is the same rows as a[0] — warp tile is 32 rows; mt splits 16+16
            // (a[0] covers m16 rows arow..; a[1] via second LDSM at +16 rows)
            {
                uint32_t off1 = (uint32_t)(arow + 16) * 128
                              + (((ks * 2 + achp) ^ ((arow + 16 + delta + 128) & 7)) << 4);
                LDSM4(a[1], Ap + off1);
            }
#pragma unroll
            for (int mt = 0; mt < 2; mt++)
#pragma unroll
                for (int nt = 0; nt < 8; nt++)
                    MMA(acc[mt][nt], a[mt], bfr[nt]);
        }
    };

    // prologue: stage 0 filled, A(1) in regs
    ldgA(0);
    stsA(0);
    cpB(0, 0);
    ldgA(1);
    asm volatile("cp.async.wait_group 0;" ::: "memory");
    __syncthreads();

#pragma unroll 1
    for (int c = 0; c < NCHUNK; c++) {
        int s = c & 1;
        if (c + 1 < NCHUNK) cpB(c + 1, s ^ 1);     // B async into other stage
        compute(c, s);
        if (c + 1 < NCHUNK) {
            stsA(s ^ 1);                           // sel-folded A for c+1
            if (c + 2 < NCHUNK) ldgA(c + 2);       // prefetch next A into regs
            asm volatile("cp.async.wait_group 0;" ::: "memory");
        }
        __syncthreads();
    }

    // epilogue
#pragma unroll
    for (int mt = 0; mt < 2; mt++) {
        int r0 = p0 + wm * 32 + mt * 16 + (lid >> 2);
#pragma unroll
        for (int nt = 0; nt < 8; nt++) {
            int col = nblk * 128 + wn * 64 + nt * 8 + (lid & 3) * 2;
            float2* d0 = (float2*)(out + (size_t)r0 * DIM + col);
            float2* d1 = (float2*)(out + (size_t)(r0 + 8) * DIM + col);
            *d0 = make_float2(acc[mt][nt][0], acc[mt][nt][1]);
            *d1 = make_float2(acc[mt][nt][2], acc[mt][nt][3]);
        }
    }
}

// ---------------------------------------------------------------- launch
extern "C" void kernel_launch(void* const* d_in, const int* in_sizes, int n_in,
                              void* d_out, int out_size)
{
    const float* x   = (const float*)d_in[0];
    const float* seg = (const float*)d_in[1];
    const float* wgt = (const float*)d_in[2];
    float* out = (float*)d_out;

    cudaFuncSetAttribute(pconv_mma, cudaFuncAttributeMaxDynamicSharedMemorySize,
                         NSTAGE * STAGE);

    prep_all<<<3888, 256>>>(x, seg, wgt);

    dim3 grid(P / 64, 2);
    pconv_mma<<<grid, 128, NSTAGE * STAGE>>>(out);
}